// round 6
// baseline (speedup 1.0000x reference)
#include <cuda_runtime.h>
#include <math.h>

#define BB 16384
#define HH 128
#define TT 20
#define PRED 30
#define G4 512          // 4*H gates
#define MT 32           // batch rows per block
#define KC 8            // k-chunk
#define NTHREADS 256

struct StepParams {
    const float* x;        // [B,2] input this step
    const float* Wih;      // [512,2]
    const float* Whh;      // [512,128]
    const float* bih;      // [512]
    const float* bhh;      // [512]
    float* h;              // [B,128] in/out
    float* c;              // [B,128] in/out
    float* fc_state;       // decoder: next-step input buffer [B,2] (else null)
    float* fc_out;         // decoder: output slice [B,2] (else null)
};

// persistent state (device globals -> no allocation)
__device__ float g_hpo[BB * HH];
__device__ float g_cpo[BB * HH];
__device__ float g_hsp[BB * HH];
__device__ float g_csp[BB * HH];
__device__ float g_hds[BB * HH];
__device__ float g_cds[BB * HH];
__device__ float g_cs[BB * 2];
__device__ float g_cp[BB * 2];

__device__ __forceinline__ float sigmoidf_(float x) { return 1.0f / (1.0f + expf(-x)); }

__global__ __launch_bounds__(NTHREADS, 2)
void lstm_step_kernel(StepParams pa, StepParams pb,
                      const float* __restrict__ Wfc, const float* __restrict__ bfc,
                      int first)
{
    const StepParams p = blockIdx.y ? pb : pa;

    __shared__ float As[MT][HH];        // h tile, row-major (reads are warp-broadcast)
    __shared__ float Ws[KC][G4 + 4];    // W chunk, [k][gate], pitch 516 (conflict-free)

    const int tid  = threadIdx.x;
    const int lane = tid & 31;
    const int warp = tid >> 5;           // 8 warps; warp handles rows warp*4..warp*4+3
    const int row0 = blockIdx.x * MT;

    float acc[4][16];

    // ---- init accumulators: bias + input-term (x is [*,2]) ----
    float x0[4], x1[4];
#pragma unroll
    for (int r = 0; r < 4; ++r) {
        int b = row0 + warp * 4 + r;
        x0[r] = p.x[b * 2 + 0];
        x1[r] = p.x[b * 2 + 1];
    }
#pragma unroll
    for (int q = 0; q < 16; ++q) {
        int g = lane + 32 * q;
        float bias = p.bih[g] + p.bhh[g];
        float wi0 = p.Wih[2 * g + 0];
        float wi1 = p.Wih[2 * g + 1];
#pragma unroll
        for (int r = 0; r < 4; ++r)
            acc[r][q] = fmaf(x1[r], wi1, fmaf(x0[r], wi0, bias));
    }

    // ---- recurrent GEMM: acc += h_tile @ Whh^T ----
    if (!first) {
        float4* As4 = reinterpret_cast<float4*>(&As[0][0]);
        const float4* h4 = reinterpret_cast<const float4*>(p.h + (size_t)row0 * HH);
#pragma unroll
        for (int i = 0; i < (MT * HH / 4) / NTHREADS; ++i)   // 4 iters
            As4[tid + i * NTHREADS] = h4[tid + i * NTHREADS];
        __syncthreads();

        for (int k0 = 0; k0 < HH; k0 += KC) {
            // load W chunk: G4 x KC (coalesced float4 along k)
#pragma unroll
            for (int i = 0; i < (G4 * KC / 4) / NTHREADS; ++i) {  // 4 iters
                int idx = tid + i * NTHREADS;
                int g = idx >> 1;
                int kf = idx & 1;
                float4 w = *reinterpret_cast<const float4*>(&p.Whh[g * HH + k0 + kf * 4]);
                Ws[kf * 4 + 0][g] = w.x;
                Ws[kf * 4 + 1][g] = w.y;
                Ws[kf * 4 + 2][g] = w.z;
                Ws[kf * 4 + 3][g] = w.w;
            }
            __syncthreads();
#pragma unroll
            for (int kk = 0; kk < KC; ++kk) {
                float a[4], bb[16];
#pragma unroll
                for (int r = 0; r < 4; ++r) a[r] = As[warp * 4 + r][k0 + kk];
#pragma unroll
                for (int q = 0; q < 16; ++q) bb[q] = Ws[kk][lane + 32 * q];
#pragma unroll
                for (int r = 0; r < 4; ++r)
#pragma unroll
                    for (int q = 0; q < 16; ++q)
                        acc[r][q] = fmaf(a[r], bb[q], acc[r][q]);
            }
            __syncthreads();
        }
    }

    // ---- LSTM cell update (cols jq, jq+4, jq+8, jq+12 are i,f,g,o of hidden j) ----
    const bool do_fc = (Wfc != nullptr);
    float wf0[4], wf1[4];
    if (do_fc) {
#pragma unroll
        for (int jq = 0; jq < 4; ++jq) {
            int j = lane + 32 * jq;
            wf0[jq] = Wfc[j];
            wf1[jq] = Wfc[HH + j];
        }
    }
#pragma unroll
    for (int r = 0; r < 4; ++r) {
        int b = row0 + warp * 4 + r;
        float f0 = 0.0f, f1 = 0.0f;
#pragma unroll
        for (int jq = 0; jq < 4; ++jq) {
            int j = lane + 32 * jq;
            size_t idx = (size_t)b * HH + j;
            float iv = sigmoidf_(acc[r][jq]);
            float fv = sigmoidf_(acc[r][jq + 4]);
            float gv = tanhf(acc[r][jq + 8]);
            float ov = sigmoidf_(acc[r][jq + 12]);
            float cold = first ? 0.0f : p.c[idx];
            float cn = fv * cold + iv * gv;
            float hv = ov * tanhf(cn);
            p.c[idx] = cn;
            p.h[idx] = hv;
            if (do_fc) {
                f0 = fmaf(hv, wf0[jq], f0);
                f1 = fmaf(hv, wf1[jq], f1);
            }
        }
        if (do_fc) {
#pragma unroll
            for (int off = 16; off > 0; off >>= 1) {
                f0 += __shfl_xor_sync(0xffffffffu, f0, off);
                f1 += __shfl_xor_sync(0xffffffffu, f1, off);
            }
            if (lane == 0) {
                float o0 = f0 + bfc[0];
                float o1 = f1 + bfc[1];
                p.fc_state[b * 2 + 0] = o0;
                p.fc_state[b * 2 + 1] = o1;
                p.fc_out[b * 2 + 0] = o0;
                p.fc_out[b * 2 + 1] = o1;
            }
        }
    }
}

// warp-per-row layernorm over 4 state arrays + decoder state combine + seed copy
__device__ __forceinline__ float4 ln4(float4 v, float4 gg, float4 bb) {
    float s  = v.x + v.y + v.z + v.w;
    float ss = v.x * v.x + v.y * v.y + v.z * v.z + v.w * v.w;
#pragma unroll
    for (int off = 16; off > 0; off >>= 1) {
        s  += __shfl_xor_sync(0xffffffffu, s, off);
        ss += __shfl_xor_sync(0xffffffffu, ss, off);
    }
    float m   = s * (1.0f / HH);
    float var = ss * (1.0f / HH) - m * m;
    float inv = rsqrtf(var + 1e-5f);
    float4 r;
    r.x = (v.x - m) * inv * gg.x + bb.x;
    r.y = (v.y - m) * inv * gg.y + bb.y;
    r.z = (v.z - m) * inv * gg.z + bb.z;
    r.w = (v.w - m) * inv * gg.w + bb.w;
    return r;
}

__global__ __launch_bounds__(NTHREADS)
void ln_combine_kernel(const float* __restrict__ ln_g, const float* __restrict__ ln_b,
                       const float* __restrict__ speed_last, const float* __restrict__ pos_last)
{
    const int tid = threadIdx.x;
    const int warp = tid >> 5;
    const int lane = tid & 31;
    const int b = blockIdx.x * 8 + warp;

    // seed decoder inputs: cs = speed[-1], cp = pos[-1]
    if (tid < 16) {
        int rb = blockIdx.x * 8 + (tid >> 1);
        g_cs[rb * 2 + (tid & 1)] = speed_last[rb * 2 + (tid & 1)];
    } else if (tid < 32) {
        int t2 = tid - 16;
        int rb = blockIdx.x * 8 + (t2 >> 1);
        g_cp[rb * 2 + (t2 & 1)] = pos_last[rb * 2 + (t2 & 1)];
    }

    size_t base = (size_t)b * HH + lane * 4;
    float4 gg = *reinterpret_cast<const float4*>(&ln_g[lane * 4]);
    float4 gb = *reinterpret_cast<const float4*>(&ln_b[lane * 4]);

    float4 hpo = ln4(*reinterpret_cast<const float4*>(&g_hpo[base]), gg, gb);
    float4 cpo = ln4(*reinterpret_cast<const float4*>(&g_cpo[base]), gg, gb);
    float4 hsp = ln4(*reinterpret_cast<const float4*>(&g_hsp[base]), gg, gb);
    float4 csp = ln4(*reinterpret_cast<const float4*>(&g_csp[base]), gg, gb);

    *reinterpret_cast<float4*>(&g_hpo[base]) = hpo;
    *reinterpret_cast<float4*>(&g_cpo[base]) = cpo;
    float4 hds = make_float4(hpo.x + hsp.x, hpo.y + hsp.y, hpo.z + hsp.z, hpo.w + hsp.w);
    float4 cds = make_float4(cpo.x + csp.x, cpo.y + csp.y, cpo.z + csp.z, cpo.w + csp.w);
    *reinterpret_cast<float4*>(&g_hds[base]) = hds;
    *reinterpret_cast<float4*>(&g_cds[base]) = cds;
}

extern "C" void kernel_launch(void* const* d_in, const int* in_sizes, int n_in,
                              void* d_out, int out_size)
{
    const float* pos    = (const float*)d_in[0];
    const float* speed  = (const float*)d_in[1];
    const float* Wih_pe = (const float*)d_in[2];
    const float* Whh_pe = (const float*)d_in[3];
    const float* bih_pe = (const float*)d_in[4];
    const float* bhh_pe = (const float*)d_in[5];
    const float* Wih_se = (const float*)d_in[6];
    const float* Whh_se = (const float*)d_in[7];
    const float* bih_se = (const float*)d_in[8];
    const float* bhh_se = (const float*)d_in[9];
    const float* ln_g   = (const float*)d_in[10];
    const float* ln_b   = (const float*)d_in[11];
    const float* Wih_sd = (const float*)d_in[12];
    const float* Whh_sd = (const float*)d_in[13];
    const float* bih_sd = (const float*)d_in[14];
    const float* bhh_sd = (const float*)d_in[15];
    const float* Wih_pd = (const float*)d_in[16];
    const float* Whh_pd = (const float*)d_in[17];
    const float* bih_pd = (const float*)d_in[18];
    const float* bhh_pd = (const float*)d_in[19];
    const float* Wfc    = (const float*)d_in[20];
    const float* bfc    = (const float*)d_in[21];

    float* out = (float*)d_out;
    float* pos_out = out;                              // [PRED, B, 2]
    float* speed_out = out + (size_t)PRED * BB * 2;    // [PRED, B, 2]

    float *hpo, *cpo, *hsp, *csp, *hds, *cds, *cs, *cp;
    cudaGetSymbolAddress((void**)&hpo, g_hpo);
    cudaGetSymbolAddress((void**)&cpo, g_cpo);
    cudaGetSymbolAddress((void**)&hsp, g_hsp);
    cudaGetSymbolAddress((void**)&csp, g_csp);
    cudaGetSymbolAddress((void**)&hds, g_hds);
    cudaGetSymbolAddress((void**)&cds, g_cds);
    cudaGetSymbolAddress((void**)&cs,  g_cs);
    cudaGetSymbolAddress((void**)&cp,  g_cp);

    dim3 grid(BB / MT, 2);

    // ---- encoders (pos + speed fused per launch) ----
    for (int t = 0; t < TT; ++t) {
        StepParams pe { pos   + (size_t)t * BB * 2, Wih_pe, Whh_pe, bih_pe, bhh_pe, hpo, cpo, nullptr, nullptr };
        StepParams se { speed + (size_t)t * BB * 2, Wih_se, Whh_se, bih_se, bhh_se, hsp, csp, nullptr, nullptr };
        lstm_step_kernel<<<grid, NTHREADS>>>(pe, se, nullptr, nullptr, (t == 0) ? 1 : 0);
    }

    // ---- layernorm + decoder-state combine + seed cs/cp ----
    ln_combine_kernel<<<BB / 8, NTHREADS>>>(ln_g, ln_b,
                                            speed + (size_t)(TT - 1) * BB * 2,
                                            pos   + (size_t)(TT - 1) * BB * 2);

    // ---- decoder (speed cell + pos cell fused per launch, FC fused) ----
    for (int t = 0; t < PRED; ++t) {
        StepParams sd { cs, Wih_sd, Whh_sd, bih_sd, bhh_sd, hds, cds, cs, speed_out + (size_t)t * BB * 2 };
        StepParams pd { cp, Wih_pd, Whh_pd, bih_pd, bhh_pd, hpo, cpo, cp, pos_out   + (size_t)t * BB * 2 };
        lstm_step_kernel<<<grid, NTHREADS>>>(sd, pd, Wfc, bfc, 0);
    }
}

// round 8
// speedup vs baseline: 1.2101x; 1.2101x over previous
#include <cuda_runtime.h>
#include <math.h>

#define BB 16384
#define HH 128
#define TT 20
#define PRED 30
#define G4 512          // 4*H gates
#define MT 32           // batch rows per block
#define KC 8            // k-chunk (double buffered)
#define NCHUNK (HH / KC)   // 16
#define NTHREADS 256

struct StepParams {
    const float* x;        // [B,2] input this step
    const float* Wih;      // [512,2]
    const float* Whh;      // [512,128]
    const float* bih;      // [512]
    const float* bhh;      // [512]
    float* h;              // [B,128] in/out
    float* c;              // [B,128] in/out
    float* fc_state;       // decoder: next-step input buffer [B,2] (else null)
    float* fc_out;         // decoder: output slice [B,2] (else null)
};

// persistent state (device globals -> no allocation)
__device__ float g_hpo[BB * HH];
__device__ float g_cpo[BB * HH];
__device__ float g_hsp[BB * HH];
__device__ float g_csp[BB * HH];
__device__ float g_hds[BB * HH];
__device__ float g_cds[BB * HH];
__device__ float g_cs[BB * 2];
__device__ float g_cp[BB * 2];

__device__ __forceinline__ float sigmoidf_(float x) { return 1.0f / (1.0f + expf(-x)); }

// Thread gate ownership: gate g(s,jj) = 128*s + 4*lane + jj  (s = i/f/g/o type, jj=0..3)
// -> thread owns hidden indices j = 4*lane + jj with all 4 gate types: cell update is
//    thread-local AND h/c global traffic is float4-coalesced.
__global__ __launch_bounds__(NTHREADS, 2)
void lstm_step_kernel(StepParams pa, StepParams pb,
                      const float* __restrict__ Wfc, const float* __restrict__ bfc,
                      int first)
{
    const StepParams p = blockIdx.y ? pb : pa;

    __shared__ float As[MT][HH];          // h tile (row-major; A reads are warp-broadcast)
    __shared__ float Ws[2][KC][G4];       // W chunk, double buffered, [k][gate]

    const int tid  = threadIdx.x;
    const int lane = tid & 31;
    const int warp = tid >> 5;            // 8 warps; warp handles rows warp*4..warp*4+3
    const int row0 = blockIdx.x * MT;
    const int g0   = 4 * lane;            // hidden base index for this thread

    float acc[4][4][4];                   // [row r][gate type s][jj]

    // ---- init accumulators: bias + input-term (x is [*,2]) ----
    float x0[4], x1[4];
#pragma unroll
    for (int r = 0; r < 4; ++r) {
        int b = row0 + warp * 4 + r;
        x0[r] = p.x[b * 2 + 0];
        x1[r] = p.x[b * 2 + 1];
    }
#pragma unroll
    for (int s = 0; s < 4; ++s) {
        int gg = 128 * s + g0;
        float4 bi = *reinterpret_cast<const float4*>(&p.bih[gg]);
        float4 bh = *reinterpret_cast<const float4*>(&p.bhh[gg]);
        float4 wA = *reinterpret_cast<const float4*>(&p.Wih[2 * gg]);      // g, g+1
        float4 wB = *reinterpret_cast<const float4*>(&p.Wih[2 * gg + 4]);  // g+2, g+3
        float wi0[4] = { wA.x, wA.z, wB.x, wB.z };
        float wi1[4] = { wA.y, wA.w, wB.y, wB.w };
        float bb4[4] = { bi.x + bh.x, bi.y + bh.y, bi.z + bh.z, bi.w + bh.w };
#pragma unroll
        for (int r = 0; r < 4; ++r)
#pragma unroll
            for (int jj = 0; jj < 4; ++jj)
                acc[r][s][jj] = fmaf(x1[r], wi1[jj], fmaf(x0[r], wi0[jj], bb4[jj]));
    }

    // ---- recurrent GEMM: acc += h_tile @ Whh^T ----
    if (!first) {
        // stage h tile
        {
            float4* As4 = reinterpret_cast<float4*>(&As[0][0]);
            const float4* h4 = reinterpret_cast<const float4*>(p.h + (size_t)row0 * HH);
#pragma unroll
            for (int i = 0; i < (MT * HH / 4) / NTHREADS; ++i)   // 4 iters
                As4[tid + i * NTHREADS] = h4[tid + i * NTHREADS];
        }

        // per-thread W chunk staging: 4 x float4 = 16 floats per chunk
        // idx = tid + i*256 -> g = idx>>1, kf = idx&1 (two float4 segments cover KC=8 k's)
        float4 wreg[4];
        const int wg[4] = { (tid + 0*NTHREADS) >> 1, (tid + 1*NTHREADS) >> 1,
                            (tid + 2*NTHREADS) >> 1, (tid + 3*NTHREADS) >> 1 };
        const int wkf  = tid & 1;

#pragma unroll
        for (int i = 0; i < 4; ++i)
            wreg[i] = *reinterpret_cast<const float4*>(&p.Whh[wg[i] * HH + 0 + wkf * 4]);
#pragma unroll
        for (int i = 0; i < 4; ++i) {
            Ws[0][wkf * 4 + 0][wg[i]] = wreg[i].x;
            Ws[0][wkf * 4 + 1][wg[i]] = wreg[i].y;
            Ws[0][wkf * 4 + 2][wg[i]] = wreg[i].z;
            Ws[0][wkf * 4 + 3][wg[i]] = wreg[i].w;
        }
        __syncthreads();

        for (int ch = 0; ch < NCHUNK; ++ch) {
            const int buf = ch & 1;
            // prefetch next chunk into registers (overlapped with compute below)
            if (ch < NCHUNK - 1) {
                int k0n = (ch + 1) * KC;
#pragma unroll
                for (int i = 0; i < 4; ++i)
                    wreg[i] = *reinterpret_cast<const float4*>(&p.Whh[wg[i] * HH + k0n + wkf * 4]);
            }

            // compute this chunk: KC k's in groups of 4
#pragma unroll
            for (int kk4 = 0; kk4 < KC / 4; ++kk4) {
                float4 a4[4];
#pragma unroll
                for (int r = 0; r < 4; ++r)
                    a4[r] = *reinterpret_cast<const float4*>(&As[warp * 4 + r][ch * KC + kk4 * 4]);
#pragma unroll
                for (int t = 0; t < 4; ++t) {
                    float4 w4[4];
#pragma unroll
                    for (int s = 0; s < 4; ++s)
                        w4[s] = *reinterpret_cast<const float4*>(&Ws[buf][kk4 * 4 + t][128 * s + g0]);
#pragma unroll
                    for (int r = 0; r < 4; ++r) {
                        float av = reinterpret_cast<const float*>(&a4[r])[t];
#pragma unroll
                        for (int s = 0; s < 4; ++s) {
                            acc[r][s][0] = fmaf(av, w4[s].x, acc[r][s][0]);
                            acc[r][s][1] = fmaf(av, w4[s].y, acc[r][s][1]);
                            acc[r][s][2] = fmaf(av, w4[s].z, acc[r][s][2]);
                            acc[r][s][3] = fmaf(av, w4[s].w, acc[r][s][3]);
                        }
                    }
                }
            }

            // store prefetched chunk into the other buffer (safe: that buffer's last
            // readers finished before the sync that ended chunk ch-1)
            if (ch < NCHUNK - 1) {
#pragma unroll
                for (int i = 0; i < 4; ++i) {
                    Ws[buf ^ 1][wkf * 4 + 0][wg[i]] = wreg[i].x;
                    Ws[buf ^ 1][wkf * 4 + 1][wg[i]] = wreg[i].y;
                    Ws[buf ^ 1][wkf * 4 + 2][wg[i]] = wreg[i].z;
                    Ws[buf ^ 1][wkf * 4 + 3][wg[i]] = wreg[i].w;
                }
            }
            __syncthreads();
        }
    }

    // ---- LSTM cell update (thread-local, float4-coalesced h/c) ----
    const bool do_fc = (Wfc != nullptr);
    float4 wfc0, wfc1;
    float bfc0 = 0.0f, bfc1 = 0.0f;
    if (do_fc) {
        wfc0 = *reinterpret_cast<const float4*>(&Wfc[g0]);
        wfc1 = *reinterpret_cast<const float4*>(&Wfc[HH + g0]);
        bfc0 = bfc[0];
        bfc1 = bfc[1];
    }
#pragma unroll
    for (int r = 0; r < 4; ++r) {
        int b = row0 + warp * 4 + r;
        size_t idx = (size_t)b * HH + g0;
        float4 cold;
        if (first) cold = make_float4(0.f, 0.f, 0.f, 0.f);
        else       cold = *reinterpret_cast<const float4*>(&p.c[idx]);
        const float* coldp = reinterpret_cast<const float*>(&cold);

        float4 cnv, hvv;
        float* cnp = reinterpret_cast<float*>(&cnv);
        float* hvp = reinterpret_cast<float*>(&hvv);
#pragma unroll
        for (int jj = 0; jj < 4; ++jj) {
            float iv = sigmoidf_(acc[r][0][jj]);
            float fv = sigmoidf_(acc[r][1][jj]);
            float gv = tanhf(acc[r][2][jj]);
            float ov = sigmoidf_(acc[r][3][jj]);
            float cn = fv * coldp[jj] + iv * gv;
            cnp[jj] = cn;
            hvp[jj] = ov * tanhf(cn);
        }
        *reinterpret_cast<float4*>(&p.c[idx]) = cnv;
        *reinterpret_cast<float4*>(&p.h[idx]) = hvv;

        if (do_fc) {
            float f0 = hvp[0] * wfc0.x + hvp[1] * wfc0.y + hvp[2] * wfc0.z + hvp[3] * wfc0.w;
            float f1 = hvp[0] * wfc1.x + hvp[1] * wfc1.y + hvp[2] * wfc1.z + hvp[3] * wfc1.w;
#pragma unroll
            for (int off = 16; off > 0; off >>= 1) {
                f0 += __shfl_xor_sync(0xffffffffu, f0, off);
                f1 += __shfl_xor_sync(0xffffffffu, f1, off);
            }
            if (lane == 0) {
                float o0 = f0 + bfc0;
                float o1 = f1 + bfc1;
                p.fc_state[b * 2 + 0] = o0;
                p.fc_state[b * 2 + 1] = o1;
                p.fc_out[b * 2 + 0] = o0;
                p.fc_out[b * 2 + 1] = o1;
            }
        }
    }
}

// warp-per-row layernorm over 4 state arrays + decoder state combine + seed copy
__device__ __forceinline__ float4 ln4(float4 v, float4 gg, float4 bb) {
    float s  = v.x + v.y + v.z + v.w;
    float ss = v.x * v.x + v.y * v.y + v.z * v.z + v.w * v.w;
#pragma unroll
    for (int off = 16; off > 0; off >>= 1) {
        s  += __shfl_xor_sync(0xffffffffu, s, off);
        ss += __shfl_xor_sync(0xffffffffu, ss, off);
    }
    float m   = s * (1.0f / HH);
    float var = ss * (1.0f / HH) - m * m;
    float inv = rsqrtf(var + 1e-5f);
    float4 r;
    r.x = (v.x - m) * inv * gg.x + bb.x;
    r.y = (v.y - m) * inv * gg.y + bb.y;
    r.z = (v.z - m) * inv * gg.z + bb.z;
    r.w = (v.w - m) * inv * gg.w + bb.w;
    return r;
}

__global__ __launch_bounds__(NTHREADS)
void ln_combine_kernel(const float* __restrict__ ln_g, const float* __restrict__ ln_b,
                       const float* __restrict__ speed_last, const float* __restrict__ pos_last)
{
    const int tid = threadIdx.x;
    const int warp = tid >> 5;
    const int lane = tid & 31;
    const int b = blockIdx.x * 8 + warp;

    // seed decoder inputs: cs = speed[-1], cp = pos[-1]
    if (tid < 16) {
        int rb = blockIdx.x * 8 + (tid >> 1);
        g_cs[rb * 2 + (tid & 1)] = speed_last[rb * 2 + (tid & 1)];
    } else if (tid < 32) {
        int t2 = tid - 16;
        int rb = blockIdx.x * 8 + (t2 >> 1);
        g_cp[rb * 2 + (t2 & 1)] = pos_last[rb * 2 + (t2 & 1)];
    }

    size_t base = (size_t)b * HH + lane * 4;
    float4 gg = *reinterpret_cast<const float4*>(&ln_g[lane * 4]);
    float4 gb = *reinterpret_cast<const float4*>(&ln_b[lane * 4]);

    float4 hpo = ln4(*reinterpret_cast<const float4*>(&g_hpo[base]), gg, gb);
    float4 cpo = ln4(*reinterpret_cast<const float4*>(&g_cpo[base]), gg, gb);
    float4 hsp = ln4(*reinterpret_cast<const float4*>(&g_hsp[base]), gg, gb);
    float4 csp = ln4(*reinterpret_cast<const float4*>(&g_csp[base]), gg, gb);

    *reinterpret_cast<float4*>(&g_hpo[base]) = hpo;
    *reinterpret_cast<float4*>(&g_cpo[base]) = cpo;
    float4 hds = make_float4(hpo.x + hsp.x, hpo.y + hsp.y, hpo.z + hsp.z, hpo.w + hsp.w);
    float4 cds = make_float4(cpo.x + csp.x, cpo.y + csp.y, cpo.z + csp.z, cpo.w + csp.w);
    *reinterpret_cast<float4*>(&g_hds[base]) = hds;
    *reinterpret_cast<float4*>(&g_cds[base]) = cds;
}

extern "C" void kernel_launch(void* const* d_in, const int* in_sizes, int n_in,
                              void* d_out, int out_size)
{
    const float* pos    = (const float*)d_in[0];
    const float* speed  = (const float*)d_in[1];
    const float* Wih_pe = (const float*)d_in[2];
    const float* Whh_pe = (const float*)d_in[3];
    const float* bih_pe = (const float*)d_in[4];
    const float* bhh_pe = (const float*)d_in[5];
    const float* Wih_se = (const float*)d_in[6];
    const float* Whh_se = (const float*)d_in[7];
    const float* bih_se = (const float*)d_in[8];
    const float* bhh_se = (const float*)d_in[9];
    const float* ln_g   = (const float*)d_in[10];
    const float* ln_b   = (const float*)d_in[11];
    const float* Wih_sd = (const float*)d_in[12];
    const float* Whh_sd = (const float*)d_in[13];
    const float* bih_sd = (const float*)d_in[14];
    const float* bhh_sd = (const float*)d_in[15];
    const float* Wih_pd = (const float*)d_in[16];
    const float* Whh_pd = (const float*)d_in[17];
    const float* bih_pd = (const float*)d_in[18];
    const float* bhh_pd = (const float*)d_in[19];
    const float* Wfc    = (const float*)d_in[20];
    const float* bfc    = (const float*)d_in[21];

    float* out = (float*)d_out;
    float* pos_out = out;                              // [PRED, B, 2]
    float* speed_out = out + (size_t)PRED * BB * 2;    // [PRED, B, 2]

    float *hpo, *cpo, *hsp, *csp, *hds, *cds, *cs, *cp;
    cudaGetSymbolAddress((void**)&hpo, g_hpo);
    cudaGetSymbolAddress((void**)&cpo, g_cpo);
    cudaGetSymbolAddress((void**)&hsp, g_hsp);
    cudaGetSymbolAddress((void**)&csp, g_csp);
    cudaGetSymbolAddress((void**)&hds, g_hds);
    cudaGetSymbolAddress((void**)&cds, g_cds);
    cudaGetSymbolAddress((void**)&cs,  g_cs);
    cudaGetSymbolAddress((void**)&cp,  g_cp);

    dim3 grid(BB / MT, 2);

    // ---- encoders (pos + speed fused per launch) ----
    for (int t = 0; t < TT; ++t) {
        StepParams pe { pos   + (size_t)t * BB * 2, Wih_pe, Whh_pe, bih_pe, bhh_pe, hpo, cpo, nullptr, nullptr };
        StepParams se { speed + (size_t)t * BB * 2, Wih_se, Whh_se, bih_se, bhh_se, hsp, csp, nullptr, nullptr };
        lstm_step_kernel<<<grid, NTHREADS>>>(pe, se, nullptr, nullptr, (t == 0) ? 1 : 0);
    }

    // ---- layernorm + decoder-state combine + seed cs/cp ----
    ln_combine_kernel<<<BB / 8, NTHREADS>>>(ln_g, ln_b,
                                            speed + (size_t)(TT - 1) * BB * 2,
                                            pos   + (size_t)(TT - 1) * BB * 2);

    // ---- decoder (speed cell + pos cell fused per launch, FC fused) ----
    for (int t = 0; t < PRED; ++t) {
        StepParams sd { cs, Wih_sd, Whh_sd, bih_sd, bhh_sd, hds, cds, cs, speed_out + (size_t)t * BB * 2 };
        StepParams pd { cp, Wih_pd, Whh_pd, bih_pd, bhh_pd, hpo, cpo, cp, pos_out   + (size_t)t * BB * 2 };
        lstm_step_kernel<<<grid, NTHREADS>>>(sd, pd, Wfc, bfc, 0);
    }
}

// round 10
// speedup vs baseline: 1.2545x; 1.0367x over previous
#include <cuda_runtime.h>
#include <math.h>

#define BB 16384
#define HH 128
#define TT 20
#define PRED 30
#define G4 512          // 4*H gates
#define MT 32           // batch rows per block
#define KC 8            // k-chunk (double buffered)
#define NCHUNK (HH / KC)   // 16
#define NTHREADS 256

struct StepParams {
    const float* x;        // [B,2] input this step
    const float* Wih;      // [512,2]
    const float* Whh;      // [512,128]
    const float* bih;      // [512]
    const float* bhh;      // [512]
    float* h;              // [B,128] in/out
    float* c;              // [B,128] in/out
    float* fc_state;       // decoder: next-step input buffer [B,2] (else null)
    float* fc_out;         // decoder: output slice [B,2] (else null)
};

// persistent state (device globals -> no allocation)
__device__ float g_hpo[BB * HH];
__device__ float g_cpo[BB * HH];
__device__ float g_hsp[BB * HH];
__device__ float g_csp[BB * HH];
__device__ float g_hds[BB * HH];
__device__ float g_cds[BB * HH];
__device__ float g_cs[BB * 2];
__device__ float g_cp[BB * 2];

__device__ __forceinline__ float sigmoidf_(float x) { return 1.0f / (1.0f + expf(-x)); }

// ---- packed f32x2 helpers (Blackwell FFMA2 path) ----
__device__ __forceinline__ unsigned long long pk2(float lo, float hi) {
    unsigned long long r;
    asm("mov.b64 %0, {%1, %2};" : "=l"(r) : "f"(lo), "f"(hi));
    return r;
}
__device__ __forceinline__ unsigned long long pkdup(float v) {
    unsigned long long r;
    asm("mov.b64 %0, {%1, %1};" : "=l"(r) : "f"(v));
    return r;
}
__device__ __forceinline__ void upk2(unsigned long long v, float& lo, float& hi) {
    asm("mov.b64 {%0, %1}, %2;" : "=f"(lo), "=f"(hi) : "l"(v));
}
__device__ __forceinline__ void fma2(unsigned long long& d, unsigned long long a, unsigned long long b) {
    asm("fma.rn.f32x2 %0, %1, %2, %0;" : "+l"(d) : "l"(a), "l"(b));
}

// Thread gate ownership: gate g(s,jj) = 128*s + 4*lane + jj  (s = i/f/g/o type, jj=0..3)
// acc kept as f32x2 pairs over jj: acc2[r][s][p] = (gate jj=2p, jj=2p+1).
__global__ __launch_bounds__(NTHREADS, 2)
void lstm_step_kernel(StepParams pa, StepParams pb,
                      const float* __restrict__ Wfc, const float* __restrict__ bfc,
                      int first)
{
    const StepParams p = blockIdx.y ? pb : pa;

    __shared__ float As[MT][HH];          // h tile (row-major; A reads are warp-broadcast)
    __shared__ float Ws[2][KC][G4];       // W chunk, double buffered, [k][gate]

    const int tid  = threadIdx.x;
    const int lane = tid & 31;
    const int warp = tid >> 5;            // 8 warps; warp handles rows warp*4..warp*4+3
    const int row0 = blockIdx.x * MT;
    const int g0   = 4 * lane;            // hidden base index for this thread

    unsigned long long acc2[4][4][2];     // [row r][gate type s][pair p]

    // ---- init accumulators: bias + input-term (x is [*,2]) ----
    float x0[4], x1[4];
#pragma unroll
    for (int r = 0; r < 4; ++r) {
        int b = row0 + warp * 4 + r;
        x0[r] = p.x[b * 2 + 0];
        x1[r] = p.x[b * 2 + 1];
    }
#pragma unroll
    for (int s = 0; s < 4; ++s) {
        int gg = 128 * s + g0;
        float4 bi = *reinterpret_cast<const float4*>(&p.bih[gg]);
        float4 bh = *reinterpret_cast<const float4*>(&p.bhh[gg]);
        float4 wA = *reinterpret_cast<const float4*>(&p.Wih[2 * gg]);      // g, g+1
        float4 wB = *reinterpret_cast<const float4*>(&p.Wih[2 * gg + 4]);  // g+2, g+3
        float wi0[4] = { wA.x, wA.z, wB.x, wB.z };
        float wi1[4] = { wA.y, wA.w, wB.y, wB.w };
        float bb4[4] = { bi.x + bh.x, bi.y + bh.y, bi.z + bh.z, bi.w + bh.w };
#pragma unroll
        for (int r = 0; r < 4; ++r) {
#pragma unroll
            for (int pp = 0; pp < 2; ++pp) {
                float v0 = fmaf(x1[r], wi1[2 * pp + 0], fmaf(x0[r], wi0[2 * pp + 0], bb4[2 * pp + 0]));
                float v1 = fmaf(x1[r], wi1[2 * pp + 1], fmaf(x0[r], wi0[2 * pp + 1], bb4[2 * pp + 1]));
                acc2[r][s][pp] = pk2(v0, v1);
            }
        }
    }

    // ---- recurrent GEMM: acc += h_tile @ Whh^T (f32x2 packed FMAs) ----
    if (!first) {
        // stage h tile
        {
            float4* As4 = reinterpret_cast<float4*>(&As[0][0]);
            const float4* h4 = reinterpret_cast<const float4*>(p.h + (size_t)row0 * HH);
#pragma unroll
            for (int i = 0; i < (MT * HH / 4) / NTHREADS; ++i)   // 4 iters
                As4[tid + i * NTHREADS] = h4[tid + i * NTHREADS];
        }

        // per-thread W chunk staging: 4 x float4 = 16 floats per chunk
        float4 wreg[4];
        const int wg[4] = { (tid + 0*NTHREADS) >> 1, (tid + 1*NTHREADS) >> 1,
                            (tid + 2*NTHREADS) >> 1, (tid + 3*NTHREADS) >> 1 };
        const int wkf  = tid & 1;

#pragma unroll
        for (int i = 0; i < 4; ++i)
            wreg[i] = *reinterpret_cast<const float4*>(&p.Whh[wg[i] * HH + 0 + wkf * 4]);
#pragma unroll
        for (int i = 0; i < 4; ++i) {
            Ws[0][wkf * 4 + 0][wg[i]] = wreg[i].x;
            Ws[0][wkf * 4 + 1][wg[i]] = wreg[i].y;
            Ws[0][wkf * 4 + 2][wg[i]] = wreg[i].z;
            Ws[0][wkf * 4 + 3][wg[i]] = wreg[i].w;
        }
        __syncthreads();

        for (int ch = 0; ch < NCHUNK; ++ch) {
            const int buf = ch & 1;
            // prefetch next chunk into registers (overlapped with compute below)
            if (ch < NCHUNK - 1) {
                int k0n = (ch + 1) * KC;
#pragma unroll
                for (int i = 0; i < 4; ++i)
                    wreg[i] = *reinterpret_cast<const float4*>(&p.Whh[wg[i] * HH + k0n + wkf * 4]);
            }

            // compute this chunk: KC k's in groups of 4
#pragma unroll
            for (int kk4 = 0; kk4 < KC / 4; ++kk4) {
                float4 a4[4];
#pragma unroll
                for (int r = 0; r < 4; ++r)
                    a4[r] = *reinterpret_cast<const float4*>(&As[warp * 4 + r][ch * KC + kk4 * 4]);
#pragma unroll
                for (int t = 0; t < 4; ++t) {
                    ulonglong2 w2[4];   // two f32x2 gate-pairs per gate type
#pragma unroll
                    for (int s = 0; s < 4; ++s)
                        w2[s] = *reinterpret_cast<const ulonglong2*>(&Ws[buf][kk4 * 4 + t][128 * s + g0]);
#pragma unroll
                    for (int r = 0; r < 4; ++r) {
                        float av = reinterpret_cast<const float*>(&a4[r])[t];
                        unsigned long long aa = pkdup(av);
#pragma unroll
                        for (int s = 0; s < 4; ++s) {
                            fma2(acc2[r][s][0], aa, w2[s].x);
                            fma2(acc2[r][s][1], aa, w2[s].y);
                        }
                    }
                }
            }

            // store prefetched chunk into the other buffer
            if (ch < NCHUNK - 1) {
#pragma unroll
                for (int i = 0; i < 4; ++i) {
                    Ws[buf ^ 1][wkf * 4 + 0][wg[i]] = wreg[i].x;
                    Ws[buf ^ 1][wkf * 4 + 1][wg[i]] = wreg[i].y;
                    Ws[buf ^ 1][wkf * 4 + 2][wg[i]] = wreg[i].z;
                    Ws[buf ^ 1][wkf * 4 + 3][wg[i]] = wreg[i].w;
                }
            }
            __syncthreads();
        }
    }

    // ---- LSTM cell update (thread-local, float4-coalesced h/c) ----
    const bool do_fc = (Wfc != nullptr);
    float4 wfc0, wfc1;
    float bfc0 = 0.0f, bfc1 = 0.0f;
    if (do_fc) {
        wfc0 = *reinterpret_cast<const float4*>(&Wfc[g0]);
        wfc1 = *reinterpret_cast<const float4*>(&Wfc[HH + g0]);
        bfc0 = bfc[0];
        bfc1 = bfc[1];
    }
#pragma unroll
    for (int r = 0; r < 4; ++r) {
        int b = row0 + warp * 4 + r;
        size_t idx = (size_t)b * HH + g0;
        float4 cold;
        if (first) cold = make_float4(0.f, 0.f, 0.f, 0.f);
        else       cold = *reinterpret_cast<const float4*>(&p.c[idx]);
        const float* coldp = reinterpret_cast<const float*>(&cold);

        // unpack gates for this row
        float ga[4][4];   // [s][jj]
#pragma unroll
        for (int s = 0; s < 4; ++s) {
            upk2(acc2[r][s][0], ga[s][0], ga[s][1]);
            upk2(acc2[r][s][1], ga[s][2], ga[s][3]);
        }

        float4 cnv, hvv;
        float* cnp = reinterpret_cast<float*>(&cnv);
        float* hvp = reinterpret_cast<float*>(&hvv);
#pragma unroll
        for (int jj = 0; jj < 4; ++jj) {
            float iv = sigmoidf_(ga[0][jj]);
            float fv = sigmoidf_(ga[1][jj]);
            float gv = tanhf(ga[2][jj]);
            float ov = sigmoidf_(ga[3][jj]);
            float cn = fv * coldp[jj] + iv * gv;
            cnp[jj] = cn;
            hvp[jj] = ov * tanhf(cn);
        }
        *reinterpret_cast<float4*>(&p.c[idx]) = cnv;
        *reinterpret_cast<float4*>(&p.h[idx]) = hvv;

        if (do_fc) {
            float f0 = hvp[0] * wfc0.x + hvp[1] * wfc0.y + hvp[2] * wfc0.z + hvp[3] * wfc0.w;
            float f1 = hvp[0] * wfc1.x + hvp[1] * wfc1.y + hvp[2] * wfc1.z + hvp[3] * wfc1.w;
#pragma unroll
            for (int off = 16; off > 0; off >>= 1) {
                f0 += __shfl_xor_sync(0xffffffffu, f0, off);
                f1 += __shfl_xor_sync(0xffffffffu, f1, off);
            }
            if (lane == 0) {
                float o0 = f0 + bfc0;
                float o1 = f1 + bfc1;
                p.fc_state[b * 2 + 0] = o0;
                p.fc_state[b * 2 + 1] = o1;
                p.fc_out[b * 2 + 0] = o0;
                p.fc_out[b * 2 + 1] = o1;
            }
        }
    }
}

// warp-per-row layernorm over 4 state arrays + decoder state combine + seed copy
__device__ __forceinline__ float4 ln4(float4 v, float4 gg, float4 bb) {
    float s  = v.x + v.y + v.z + v.w;
    float ss = v.x * v.x + v.y * v.y + v.z * v.z + v.w * v.w;
#pragma unroll
    for (int off = 16; off > 0; off >>= 1) {
        s  += __shfl_xor_sync(0xffffffffu, s, off);
        ss += __shfl_xor_sync(0xffffffffu, ss, off);
    }
    float m   = s * (1.0f / HH);
    float var = ss * (1.0f / HH) - m * m;
    float inv = rsqrtf(var + 1e-5f);
    float4 r;
    r.x = (v.x - m) * inv * gg.x + bb.x;
    r.y = (v.y - m) * inv * gg.y + bb.y;
    r.z = (v.z - m) * inv * gg.z + bb.z;
    r.w = (v.w - m) * inv * gg.w + bb.w;
    return r;
}

__global__ __launch_bounds__(NTHREADS)
void ln_combine_kernel(const float* __restrict__ ln_g, const float* __restrict__ ln_b,
                       const float* __restrict__ speed_last, const float* __restrict__ pos_last)
{
    const int tid = threadIdx.x;
    const int warp = tid >> 5;
    const int lane = tid & 31;
    const int b = blockIdx.x * 8 + warp;

    // seed decoder inputs: cs = speed[-1], cp = pos[-1]
    if (tid < 16) {
        int rb = blockIdx.x * 8 + (tid >> 1);
        g_cs[rb * 2 + (tid & 1)] = speed_last[rb * 2 + (tid & 1)];
    } else if (tid < 32) {
        int t2 = tid - 16;
        int rb = blockIdx.x * 8 + (t2 >> 1);
        g_cp[rb * 2 + (t2 & 1)] = pos_last[rb * 2 + (t2 & 1)];
    }

    size_t base = (size_t)b * HH + lane * 4;
    float4 gg = *reinterpret_cast<const float4*>(&ln_g[lane * 4]);
    float4 gb = *reinterpret_cast<const float4*>(&ln_b[lane * 4]);

    float4 hpo = ln4(*reinterpret_cast<const float4*>(&g_hpo[base]), gg, gb);
    float4 cpo = ln4(*reinterpret_cast<const float4*>(&g_cpo[base]), gg, gb);
    float4 hsp = ln4(*reinterpret_cast<const float4*>(&g_hsp[base]), gg, gb);
    float4 csp = ln4(*reinterpret_cast<const float4*>(&g_csp[base]), gg, gb);

    *reinterpret_cast<float4*>(&g_hpo[base]) = hpo;
    *reinterpret_cast<float4*>(&g_cpo[base]) = cpo;
    float4 hds = make_float4(hpo.x + hsp.x, hpo.y + hsp.y, hpo.z + hsp.z, hpo.w + hsp.w);
    float4 cds = make_float4(cpo.x + csp.x, cpo.y + csp.y, cpo.z + csp.z, cpo.w + csp.w);
    *reinterpret_cast<float4*>(&g_hds[base]) = hds;
    *reinterpret_cast<float4*>(&g_cds[base]) = cds;
}

extern "C" void kernel_launch(void* const* d_in, const int* in_sizes, int n_in,
                              void* d_out, int out_size)
{
    const float* pos    = (const float*)d_in[0];
    const float* speed  = (const float*)d_in[1];
    const float* Wih_pe = (const float*)d_in[2];
    const float* Whh_pe = (const float*)d_in[3];
    const float* bih_pe = (const float*)d_in[4];
    const float* bhh_pe = (const float*)d_in[5];
    const float* Wih_se = (const float*)d_in[6];
    const float* Whh_se = (const float*)d_in[7];
    const float* bih_se = (const float*)d_in[8];
    const float* bhh_se = (const float*)d_in[9];
    const float* ln_g   = (const float*)d_in[10];
    const float* ln_b   = (const float*)d_in[11];
    const float* Wih_sd = (const float*)d_in[12];
    const float* Whh_sd = (const float*)d_in[13];
    const float* bih_sd = (const float*)d_in[14];
    const float* bhh_sd = (const float*)d_in[15];
    const float* Wih_pd = (const float*)d_in[16];
    const float* Whh_pd = (const float*)d_in[17];
    const float* bih_pd = (const float*)d_in[18];
    const float* bhh_pd = (const float*)d_in[19];
    const float* Wfc    = (const float*)d_in[20];
    const float* bfc    = (const float*)d_in[21];

    float* out = (float*)d_out;
    float* pos_out = out;                              // [PRED, B, 2]
    float* speed_out = out + (size_t)PRED * BB * 2;    // [PRED, B, 2]

    float *hpo, *cpo, *hsp, *csp, *hds, *cds, *cs, *cp;
    cudaGetSymbolAddress((void**)&hpo, g_hpo);
    cudaGetSymbolAddress((void**)&cpo, g_cpo);
    cudaGetSymbolAddress((void**)&hsp, g_hsp);
    cudaGetSymbolAddress((void**)&csp, g_csp);
    cudaGetSymbolAddress((void**)&hds, g_hds);
    cudaGetSymbolAddress((void**)&cds, g_cds);
    cudaGetSymbolAddress((void**)&cs,  g_cs);
    cudaGetSymbolAddress((void**)&cp,  g_cp);

    dim3 grid(BB / MT, 2);

    // ---- encoders (pos + speed fused per launch) ----
    for (int t = 0; t < TT; ++t) {
        StepParams pe { pos   + (size_t)t * BB * 2, Wih_pe, Whh_pe, bih_pe, bhh_pe, hpo, cpo, nullptr, nullptr };
        StepParams se { speed + (size_t)t * BB * 2, Wih_se, Whh_se, bih_se, bhh_se, hsp, csp, nullptr, nullptr };
        lstm_step_kernel<<<grid, NTHREADS>>>(pe, se, nullptr, nullptr, (t == 0) ? 1 : 0);
    }

    // ---- layernorm + decoder-state combine + seed cs/cp ----
    ln_combine_kernel<<<BB / 8, NTHREADS>>>(ln_g, ln_b,
                                            speed + (size_t)(TT - 1) * BB * 2,
                                            pos   + (size_t)(TT - 1) * BB * 2);

    // ---- decoder (speed cell + pos cell fused per launch, FC fused) ----
    for (int t = 0; t < PRED; ++t) {
        StepParams sd { cs, Wih_sd, Whh_sd, bih_sd, bhh_sd, hds, cds, cs, speed_out + (size_t)t * BB * 2 };
        StepParams pd { cp, Wih_pd, Whh_pd, bih_pd, bhh_pd, hpo, cpo, cp, pos_out   + (size_t)t * BB * 2 };
        lstm_step_kernel<<<grid, NTHREADS>>>(sd, pd, Wfc, bfc, 0);
    }
}